// round 6
// baseline (speedup 1.0000x reference)
#include <cuda_runtime.h>
#include <cuda_bf16.h>
#include <cuda_fp16.h>

// GCN 2-layer forward, pull-based aggregation via per-launch CSR build.
//   t1h = fp16( dinv[i] * (x @ W1) )             [tf32 tensor-core GEMM]
//   r   = relu(dinv[i] * (t1h[i] + sum t1h[src]) + b1)   [fp32 accum]
//   t2h = fp16( dinv[i] * (r @ W2) )             [tf32 tensor-core GEMM]
//   out = dinv[i] * (t2h[i] + sum t2h[src]) + b2 [fp32 accum]

#define MAXN 50000
#define MAXE 800000
#define C1 128
#define C2 64

__device__ int    g_is64;
__device__ int    g_cnt[MAXN];
__device__ int    g_off[MAXN + 1];
__device__ int    g_cur[MAXN];
__device__ int    g_srcl[MAXE];
__device__ int    g_part[64];
__device__ float  g_dinv[MAXN];
__device__ __half g_t1h[MAXN * C1];
__device__ float  g_r[MAXN * C1];
__device__ __half g_t2h[MAXN * C2];

// ---------------------------------------------------------------------------
__global__ void k_detect(const void* ei, int n_nodes, long long safe_words) {
    if (threadIdx.x == 0 && blockIdx.x == 0) {
        const unsigned long long* p = (const unsigned long long*)ei;
        long long cnt = safe_words < 64 ? safe_words : 64;
        int ok64 = 1;
        for (long long i = 0; i < cnt; i++) {
            if (p[i] >= (unsigned long long)n_nodes) { ok64 = 0; break; }
        }
        g_is64 = ok64;
    }
}

__device__ __forceinline__ int load_edge(const void* ei, long long idx, int is64) {
    if (is64) return (int)((const long long*)ei)[idx];
    return ((const int*)ei)[idx];
}

__global__ void k_zero_cnt(int n) {
    int i = blockIdx.x * blockDim.x + threadIdx.x;
    if (i < n) g_cnt[i] = 0;
}

__global__ void k_count(const void* ei, long long E) {
    long long e = (long long)blockIdx.x * blockDim.x + threadIdx.x;
    if (e < E) {
        int d = load_edge(ei, E + e, g_is64);
        atomicAdd(&g_cnt[d], 1);
    }
}

// ---------------------------------------------------------------------------
// Shuffle-based exclusive scan: 256 thr/block, 8 elems/thread => 2048/block.
#define SCAN_TPB 256
#define SCAN_EPT 8
#define SCAN_BLK (SCAN_TPB * SCAN_EPT)

__global__ __launch_bounds__(SCAN_TPB) void k_scan1(int n) {
    __shared__ int wsum[8];
    int tid  = threadIdx.x;
    int lane = tid & 31;
    int wrp  = tid >> 5;
    int base = blockIdx.x * SCAN_BLK + tid * SCAN_EPT;

    int v[SCAN_EPT];
    // vectorized load (g_cnt zero-padded region is safe: MAXN rounding handled by bounds)
#pragma unroll
    for (int i = 0; i < SCAN_EPT; i++)
        v[i] = (base + i < n) ? g_cnt[base + i] : 0;

    int local = 0;
#pragma unroll
    for (int i = 0; i < SCAN_EPT; i++) { int t = v[i]; v[i] = local; local += t; }

    // warp inclusive scan of thread totals
    int incl = local;
#pragma unroll
    for (int o = 1; o < 32; o <<= 1) {
        int t = __shfl_up_sync(0xffffffffu, incl, o);
        if (lane >= o) incl += t;
    }
    if (lane == 31) wsum[wrp] = incl;
    __syncthreads();
    if (wrp == 0) {
        int w = (lane < 8) ? wsum[lane] : 0;
#pragma unroll
        for (int o = 1; o < 8; o <<= 1) {
            int t = __shfl_up_sync(0xffffffffu, w, o);
            if (lane >= o) w += t;
        }
        if (lane < 8) wsum[lane] = w;
    }
    __syncthreads();

    int warpExcl = (wrp == 0) ? 0 : wsum[wrp - 1];
    int thrExcl  = warpExcl + incl - local;   // exclusive prefix of this thread
#pragma unroll
    for (int i = 0; i < SCAN_EPT; i++)
        if (base + i < n) g_off[base + i] = thrExcl + v[i];

    if (tid == SCAN_TPB - 1) g_part[blockIdx.x] = warpExcl + incl;
}

__global__ void k_scan2(int nb) {
    int lane = threadIdx.x;
    int v = (lane < nb) ? g_part[lane] : 0;
#pragma unroll
    for (int o = 1; o < 32; o <<= 1) {
        int t = __shfl_up_sync(0xffffffffu, v, o);
        if (lane >= o) v += t;
    }
    if (lane < nb) g_part[lane] = v;  // inclusive; scan3 uses [b-1]
}

__global__ void k_scan3(int n, long long E) {
    int i = blockIdx.x * blockDim.x + threadIdx.x;
    if (i < n) {
        int b = i / SCAN_BLK;
        int off = g_off[i] + (b > 0 ? g_part[b - 1] : 0);
        g_off[i] = off;
        g_cur[i] = off;
        g_dinv[i] = rsqrtf((float)(g_cnt[i] + 1));
    }
    if (i == 0) g_off[n] = (int)E;
}

__global__ void k_bucket(const void* ei, long long E) {
    long long e = (long long)blockIdx.x * blockDim.x + threadIdx.x;
    if (e < E) {
        int is64 = g_is64;
        int s = load_edge(ei, e, is64);
        int d = load_edge(ei, E + e, is64);
        int pos = atomicAdd(&g_cur[d], 1);
        g_srcl[pos] = s;
    }
}

// ---------------------------------------------------------------------------
// tf32 tensor-core GEMM: C[m][c] = fp16( dinv[m] * sum_k A[m][k] * W[k][c] )
__device__ __forceinline__ unsigned f2tf32(float f) {
    unsigned u;
    asm("cvt.rna.tf32.f32 %0, %1;" : "=r"(u) : "f"(f));
    return u;
}

template <int NC>
__global__ __launch_bounds__(256) void k_gemm_tf32(
    const float* __restrict__ A, const float* __restrict__ W,
    __half* __restrict__ C, int M)
{
    constexpr int K   = 128;
    constexpr int BM  = 128;
    constexpr int BK  = 32;
    constexpr int PA  = BK + 4;
    constexpr int PB  = NC + 4;
    constexpr int NF  = NC / 16;

    __shared__ unsigned As[BM * PA];
    __shared__ unsigned Bs[BK * PB];

    int tid  = threadIdx.x;
    int wid  = tid >> 5;
    int lane = tid & 31;
    int wm   = wid >> 1;
    int wn   = wid & 1;
    int g    = lane >> 2;
    int t    = lane & 3;
    int rowBase = blockIdx.x * BM;

    float acc[2][NF][4];
#pragma unroll
    for (int mf = 0; mf < 2; mf++)
#pragma unroll
        for (int nf = 0; nf < NF; nf++)
#pragma unroll
            for (int i = 0; i < 4; i++) acc[mf][nf][i] = 0.0f;

    for (int kc = 0; kc < K; kc += BK) {
#pragma unroll
        for (int it = 0; it < (BM * BK / 4) / 256; it++) {
            int idx = tid + it * 256;
            int row = idx >> 3;
            int c4  = (idx & 7) * 4;
            int gr  = rowBase + row;
            float4 av = make_float4(0.f, 0.f, 0.f, 0.f);
            if (gr < M) av = *(const float4*)&A[(long long)gr * K + kc + c4];
            unsigned* dst = &As[row * PA + c4];
            dst[0] = f2tf32(av.x); dst[1] = f2tf32(av.y);
            dst[2] = f2tf32(av.z); dst[3] = f2tf32(av.w);
        }
#pragma unroll
        for (int it = 0; it < (BK * NC / 4) / 256; it++) {
            int idx = tid + it * 256;
            int row = idx / (NC / 4);
            int c4  = (idx % (NC / 4)) * 4;
            float4 bv = *(const float4*)&W[(kc + row) * NC + c4];
            unsigned* dst = &Bs[row * PB + c4];
            dst[0] = f2tf32(bv.x); dst[1] = f2tf32(bv.y);
            dst[2] = f2tf32(bv.z); dst[3] = f2tf32(bv.w);
        }
        __syncthreads();

#pragma unroll
        for (int kk = 0; kk < BK; kk += 8) {
            unsigned a[2][4];
#pragma unroll
            for (int mf = 0; mf < 2; mf++) {
                int r0 = wm * 32 + mf * 16;
                a[mf][0] = As[(r0 + g)     * PA + kk + t];
                a[mf][1] = As[(r0 + g + 8) * PA + kk + t];
                a[mf][2] = As[(r0 + g)     * PA + kk + t + 4];
                a[mf][3] = As[(r0 + g + 8) * PA + kk + t + 4];
            }
            unsigned b[NF][2];
#pragma unroll
            for (int nf = 0; nf < NF; nf++) {
                int c0 = wn * NF * 8 + nf * 8 + g;
                b[nf][0] = Bs[(kk + t)     * PB + c0];
                b[nf][1] = Bs[(kk + t + 4) * PB + c0];
            }
#pragma unroll
            for (int mf = 0; mf < 2; mf++)
#pragma unroll
                for (int nf = 0; nf < NF; nf++) {
                    asm volatile(
                        "mma.sync.aligned.m16n8k8.row.col.f32.tf32.tf32.f32 "
                        "{%0,%1,%2,%3}, {%4,%5,%6,%7}, {%8,%9}, {%0,%1,%2,%3};\n"
                        : "+f"(acc[mf][nf][0]), "+f"(acc[mf][nf][1]),
                          "+f"(acc[mf][nf][2]), "+f"(acc[mf][nf][3])
                        : "r"(a[mf][0]), "r"(a[mf][1]), "r"(a[mf][2]), "r"(a[mf][3]),
                          "r"(b[nf][0]), "r"(b[nf][1]));
                }
        }
        __syncthreads();
    }

#pragma unroll
    for (int mf = 0; mf < 2; mf++) {
        int r0 = rowBase + wm * 32 + mf * 16 + g;
        int r1 = r0 + 8;
        float d0 = (r0 < M) ? g_dinv[r0] : 0.f;
        float d1 = (r1 < M) ? g_dinv[r1] : 0.f;
#pragma unroll
        for (int nf = 0; nf < NF; nf++) {
            int col = wn * NF * 8 + nf * 8 + 2 * t;
            if (r0 < M) {
                __half2 h0 = __floats2half2_rn(d0 * acc[mf][nf][0], d0 * acc[mf][nf][1]);
                *(__half2*)&C[(long long)r0 * NC + col] = h0;
            }
            if (r1 < M) {
                __half2 h1 = __floats2half2_rn(d1 * acc[mf][nf][2], d1 * acc[mf][nf][3]);
                *(__half2*)&C[(long long)r1 * NC + col] = h1;
            }
        }
    }
}

// ---------------------------------------------------------------------------
// Pull layer 1: warp per node, 128 fp16 ch (uint2/lane), x4-unrolled gathers.
__global__ __launch_bounds__(256) void k_pull1(const float* __restrict__ b1, int n) {
    int w = (blockIdx.x * blockDim.x + threadIdx.x) >> 5;
    int lane = threadIdx.x & 31;
    if (w >= n) return;
    const uint2* t1v = (const uint2*)g_t1h;

    uint2 sv = t1v[(long long)w * 32 + lane];
    float2 f0 = __half22float2(*(__half2*)&sv.x);
    float2 f1 = __half22float2(*(__half2*)&sv.y);
    float4 acc = make_float4(f0.x, f0.y, f1.x, f1.y);

    int e0 = g_off[w], e1 = g_off[w + 1];
    int e = e0;
    for (; e + 4 <= e1; e += 4) {
        int s0 = g_srcl[e];
        int s1 = g_srcl[e + 1];
        int s2 = g_srcl[e + 2];
        int s3 = g_srcl[e + 3];
        uint2 v0 = t1v[(long long)s0 * 32 + lane];
        uint2 v1 = t1v[(long long)s1 * 32 + lane];
        uint2 v2 = t1v[(long long)s2 * 32 + lane];
        uint2 v3 = t1v[(long long)s3 * 32 + lane];
#define ACC1(V) { \
        float2 a_ = __half22float2(*(__half2*)&(V).x); \
        float2 b_ = __half22float2(*(__half2*)&(V).y); \
        acc.x += a_.x; acc.y += a_.y; acc.z += b_.x; acc.w += b_.y; }
        ACC1(v0) ACC1(v1) ACC1(v2) ACC1(v3)
    }
    for (; e < e1; e++) {
        uint2 v = t1v[(long long)g_srcl[e] * 32 + lane];
        ACC1(v)
    }
#undef ACC1
    float di = g_dinv[w];
    float4 bb = ((const float4*)b1)[lane];
    float4 r;
    r.x = fmaxf(fmaf(di, acc.x, bb.x), 0.0f);
    r.y = fmaxf(fmaf(di, acc.y, bb.y), 0.0f);
    r.z = fmaxf(fmaf(di, acc.z, bb.z), 0.0f);
    r.w = fmaxf(fmaf(di, acc.w, bb.w), 0.0f);
    ((float4*)g_r)[(long long)w * 32 + lane] = r;
}

// Pull layer 2: warp per node, 64 fp16 ch (uint/lane = 2 halves), x4-unrolled.
__global__ __launch_bounds__(256) void k_pull2(const float* __restrict__ b2,
                                               float* __restrict__ out, int n) {
    int w = (blockIdx.x * blockDim.x + threadIdx.x) >> 5;
    int lane = threadIdx.x & 31;
    if (w >= n) return;
    const unsigned* t2v = (const unsigned*)g_t2h;

    unsigned sv = t2v[(long long)w * 32 + lane];
    float2 acc = __half22float2(*(__half2*)&sv);

    int e0 = g_off[w], e1 = g_off[w + 1];
    int e = e0;
    for (; e + 4 <= e1; e += 4) {
        int s0 = g_srcl[e];
        int s1 = g_srcl[e + 1];
        int s2 = g_srcl[e + 2];
        int s3 = g_srcl[e + 3];
        unsigned v0 = t2v[(long long)s0 * 32 + lane];
        unsigned v1 = t2v[(long long)s1 * 32 + lane];
        unsigned v2 = t2v[(long long)s2 * 32 + lane];
        unsigned v3 = t2v[(long long)s3 * 32 + lane];
#define ACC2(V) { float2 a_ = __half22float2(*(__half2*)&(V)); acc.x += a_.x; acc.y += a_.y; }
        ACC2(v0) ACC2(v1) ACC2(v2) ACC2(v3)
    }
    for (; e < e1; e++) {
        unsigned v = t2v[(long long)g_srcl[e] * 32 + lane];
        ACC2(v)
    }
#undef ACC2
    float di = g_dinv[w];
    float2 bb = ((const float2*)b2)[lane];
    float2 r;
    r.x = fmaf(di, acc.x, bb.x);
    r.y = fmaf(di, acc.y, bb.y);
    ((float2*)out)[(long long)w * 32 + lane] = r;
}

// ---------------------------------------------------------------------------
// GEMM2 takes fp32 input r; reuse same kernel via a cast wrapper not needed:
// k_gemm_tf32 expects float A — g_r is fp32. Both GEMMs output fp16.

extern "C" void kernel_launch(void* const* d_in, const int* in_sizes, int n_in,
                              void* d_out, int out_size) {
    const float* x  = (const float*)d_in[0];
    const void*  ei = d_in[1];
    const float* W1 = (const float*)d_in[2];
    const float* b1 = (const float*)d_in[3];
    const float* W2 = (const float*)d_in[4];
    const float* b2 = (const float*)d_in[5];
    float* out = (float*)d_out;

    int N = in_sizes[0] / C1;            // 50000
    long long E = in_sizes[1] / 2;       // 800000

    void *p_t1h = nullptr, *p_r = nullptr, *p_t2h = nullptr;
    cudaGetSymbolAddress(&p_t1h, g_t1h);
    cudaGetSymbolAddress(&p_r,   g_r);
    cudaGetSymbolAddress(&p_t2h, g_t2h);

    k_detect<<<1, 32>>>(ei, N, E);

    int gN = (N + 255) / 256;
    long long gE = (E + 255) / 256;

    k_zero_cnt<<<gN, 256>>>(N);
    k_count<<<(unsigned)gE, 256>>>(ei, E);

    int nb = (N + SCAN_BLK - 1) / SCAN_BLK;   // 25
    k_scan1<<<nb, SCAN_TPB>>>(N);
    k_scan2<<<1, 32>>>(nb);
    k_scan3<<<gN, 256>>>(N, E);
    k_bucket<<<(unsigned)gE, 256>>>(ei, E);

    int gg = (N + 127) / 128;
    k_gemm_tf32<C1><<<gg, 256>>>(x, W1, (__half*)p_t1h, N);

    long long warpThreads = (long long)N * 32;
    int gw = (int)((warpThreads + 255) / 256);
    k_pull1<<<gw, 256>>>(b1, N);

    k_gemm_tf32<C2><<<gg, 256>>>((const float*)p_r, W2, (__half*)p_t2h, N);

    k_pull2<<<gw, 256>>>(b2, out, N);
}

// round 7
// speedup vs baseline: 1.4545x; 1.4545x over previous
#include <cuda_runtime.h>
#include <cuda_bf16.h>
#include <cuda_fp16.h>

// GCN 2-layer forward, pull-based aggregation via per-launch CSR build.
//   t1h = fp16( dinv[i] * (x @ W1) )             [tf32 tensor-core GEMM]
//   r   = relu(dinv[i] * (t1h[i] + sum t1h[src]) + b1)   [fp32 accum]
//   t2h = fp16( dinv[i] * (r @ W2) )             [tf32 tensor-core GEMM]
//   out = dinv[i] * (t2h[i] + sum t2h[src]) + b2 [fp32 accum]

#define MAXN 50000
#define MAXE 800000
#define C1 128
#define C2 64

__device__ int    g_is64;
__device__ int    g_cnt[MAXN];
__device__ int    g_off[MAXN + 1];
__device__ int    g_cur[MAXN];
__device__ int    g_srcl[MAXE];
__device__ int    g_part[64];
__device__ float  g_dinv[MAXN];
__device__ __half g_t1h[MAXN * C1];
__device__ float  g_r[MAXN * C1];
__device__ __half g_t2h[MAXN * C2];

// ---------------------------------------------------------------------------
__global__ void k_detect(const void* ei, int n_nodes, long long safe_words) {
    if (threadIdx.x == 0 && blockIdx.x == 0) {
        const unsigned long long* p = (const unsigned long long*)ei;
        long long cnt = safe_words < 64 ? safe_words : 64;
        int ok64 = 1;
        for (long long i = 0; i < cnt; i++) {
            if (p[i] >= (unsigned long long)n_nodes) { ok64 = 0; break; }
        }
        g_is64 = ok64;
    }
}

__device__ __forceinline__ int load_edge(const void* ei, long long idx, int is64) {
    if (is64) return (int)((const long long*)ei)[idx];
    return ((const int*)ei)[idx];
}

__global__ void k_zero_cnt(int n) {
    int i = blockIdx.x * blockDim.x + threadIdx.x;
    if (i < n) g_cnt[i] = 0;
}

__global__ void k_count(const void* ei, long long E) {
    long long e = (long long)blockIdx.x * blockDim.x + threadIdx.x;
    if (e < E) {
        int d = load_edge(ei, E + e, g_is64);
        atomicAdd(&g_cnt[d], 1);
    }
}

// Two-level exclusive scan of g_cnt -> g_off  (R5 proven version)
__global__ void k_scan1(int n) {
    __shared__ int s[1024];
    int tid = threadIdx.x;
    int gid = blockIdx.x * 1024 + tid;
    int v = (gid < n) ? g_cnt[gid] : 0;
    s[tid] = v;
    __syncthreads();
#pragma unroll
    for (int o = 1; o < 1024; o <<= 1) {
        int t = (tid >= o) ? s[tid - o] : 0;
        __syncthreads();
        s[tid] += t;
        __syncthreads();
    }
    if (gid < n) g_off[gid] = s[tid] - v;
    if (tid == 1023) g_part[blockIdx.x] = s[tid];
}

__global__ void k_scan2(int nb) {
    __shared__ int s[64];
    int tid = threadIdx.x;
    int v = (tid < nb) ? g_part[tid] : 0;
    s[tid] = v;
    __syncthreads();
#pragma unroll
    for (int o = 1; o < 64; o <<= 1) {
        int t = (tid >= o) ? s[tid - o] : 0;
        __syncthreads();
        s[tid] += t;
        __syncthreads();
    }
    if (tid < nb) g_part[tid] = s[tid] - v;
}

__global__ void k_scan3(int n, long long E) {
    int i = blockIdx.x * blockDim.x + threadIdx.x;
    if (i < n) {
        int off = g_off[i] + g_part[i >> 10];
        g_off[i] = off;
        g_cur[i] = off;
        g_dinv[i] = rsqrtf((float)(g_cnt[i] + 1));
    }
    if (i == 0) g_off[n] = (int)E;
}

__global__ void k_bucket(const void* ei, long long E) {
    long long e = (long long)blockIdx.x * blockDim.x + threadIdx.x;
    if (e < E) {
        int is64 = g_is64;
        int s = load_edge(ei, e, is64);
        int d = load_edge(ei, E + e, is64);
        int pos = atomicAdd(&g_cur[d], 1);
        g_srcl[pos] = s;
    }
}

// ---------------------------------------------------------------------------
// tf32 tensor-core GEMM: C[m][c] = fp16( dinv[m] * sum_k A[m][k] * W[k][c] )
__device__ __forceinline__ unsigned f2tf32(float f) {
    unsigned u;
    asm("cvt.rna.tf32.f32 %0, %1;" : "=r"(u) : "f"(f));
    return u;
}

template <int NC>
__global__ __launch_bounds__(256) void k_gemm_tf32(
    const float* __restrict__ A, const float* __restrict__ W,
    __half* __restrict__ C, int M)
{
    constexpr int K   = 128;
    constexpr int BM  = 128;
    constexpr int BK  = 32;
    constexpr int PA  = BK + 4;
    constexpr int PB  = NC + 4;
    constexpr int NF  = NC / 16;

    __shared__ unsigned As[BM * PA];
    __shared__ unsigned Bs[BK * PB];

    int tid  = threadIdx.x;
    int wid  = tid >> 5;
    int lane = tid & 31;
    int wm   = wid >> 1;
    int wn   = wid & 1;
    int g    = lane >> 2;
    int t    = lane & 3;
    int rowBase = blockIdx.x * BM;

    float acc[2][NF][4];
#pragma unroll
    for (int mf = 0; mf < 2; mf++)
#pragma unroll
        for (int nf = 0; nf < NF; nf++)
#pragma unroll
            for (int i = 0; i < 4; i++) acc[mf][nf][i] = 0.0f;

    for (int kc = 0; kc < K; kc += BK) {
#pragma unroll
        for (int it = 0; it < (BM * BK / 4) / 256; it++) {
            int idx = tid + it * 256;
            int row = idx >> 3;
            int c4  = (idx & 7) * 4;
            int gr  = rowBase + row;
            float4 av = make_float4(0.f, 0.f, 0.f, 0.f);
            if (gr < M) av = *(const float4*)&A[(long long)gr * K + kc + c4];
            unsigned* dst = &As[row * PA + c4];
            dst[0] = f2tf32(av.x); dst[1] = f2tf32(av.y);
            dst[2] = f2tf32(av.z); dst[3] = f2tf32(av.w);
        }
#pragma unroll
        for (int it = 0; it < (BK * NC / 4) / 256; it++) {
            int idx = tid + it * 256;
            int row = idx / (NC / 4);
            int c4  = (idx % (NC / 4)) * 4;
            float4 bv = *(const float4*)&W[(kc + row) * NC + c4];
            unsigned* dst = &Bs[row * PB + c4];
            dst[0] = f2tf32(bv.x); dst[1] = f2tf32(bv.y);
            dst[2] = f2tf32(bv.z); dst[3] = f2tf32(bv.w);
        }
        __syncthreads();

#pragma unroll
        for (int kk = 0; kk < BK; kk += 8) {
            unsigned a[2][4];
#pragma unroll
            for (int mf = 0; mf < 2; mf++) {
                int r0 = wm * 32 + mf * 16;
                a[mf][0] = As[(r0 + g)     * PA + kk + t];
                a[mf][1] = As[(r0 + g + 8) * PA + kk + t];
                a[mf][2] = As[(r0 + g)     * PA + kk + t + 4];
                a[mf][3] = As[(r0 + g + 8) * PA + kk + t + 4];
            }
            unsigned b[NF][2];
#pragma unroll
            for (int nf = 0; nf < NF; nf++) {
                int c0 = wn * NF * 8 + nf * 8 + g;
                b[nf][0] = Bs[(kk + t)     * PB + c0];
                b[nf][1] = Bs[(kk + t + 4) * PB + c0];
            }
#pragma unroll
            for (int mf = 0; mf < 2; mf++)
#pragma unroll
                for (int nf = 0; nf < NF; nf++) {
                    asm volatile(
                        "mma.sync.aligned.m16n8k8.row.col.f32.tf32.tf32.f32 "
                        "{%0,%1,%2,%3}, {%4,%5,%6,%7}, {%8,%9}, {%0,%1,%2,%3};\n"
                        : "+f"(acc[mf][nf][0]), "+f"(acc[mf][nf][1]),
                          "+f"(acc[mf][nf][2]), "+f"(acc[mf][nf][3])
                        : "r"(a[mf][0]), "r"(a[mf][1]), "r"(a[mf][2]), "r"(a[mf][3]),
                          "r"(b[nf][0]), "r"(b[nf][1]));
                }
        }
        __syncthreads();
    }

#pragma unroll
    for (int mf = 0; mf < 2; mf++) {
        int r0 = rowBase + wm * 32 + mf * 16 + g;
        int r1 = r0 + 8;
        float d0 = (r0 < M) ? g_dinv[r0] : 0.f;
        float d1 = (r1 < M) ? g_dinv[r1] : 0.f;
#pragma unroll
        for (int nf = 0; nf < NF; nf++) {
            int col = wn * NF * 8 + nf * 8 + 2 * t;
            if (r0 < M) {
                __half2 h0 = __floats2half2_rn(d0 * acc[mf][nf][0], d0 * acc[mf][nf][1]);
                *(__half2*)&C[(long long)r0 * NC + col] = h0;
            }
            if (r1 < M) {
                __half2 h1 = __floats2half2_rn(d1 * acc[mf][nf][2], d1 * acc[mf][nf][3]);
                *(__half2*)&C[(long long)r1 * NC + col] = h1;
            }
        }
    }
}

// ---------------------------------------------------------------------------
// Pull layer 1: warp per node, 128 fp16 channels (uint2/lane), serial loop
// (NO unroll — R6 showed front-batched gathers trigger L1tex-queue spread).
__global__ __launch_bounds__(256) void k_pull1(const float* __restrict__ b1, int n) {
    int w = (blockIdx.x * blockDim.x + threadIdx.x) >> 5;
    int lane = threadIdx.x & 31;
    if (w >= n) return;
    const uint2* t1v = (const uint2*)g_t1h;

    uint2 sv = t1v[(long long)w * 32 + lane];
    float2 f0 = __half22float2(*(__half2*)&sv.x);
    float2 f1 = __half22float2(*(__half2*)&sv.y);
    float4 acc = make_float4(f0.x, f0.y, f1.x, f1.y);

    int e0 = g_off[w], e1 = g_off[w + 1];
    for (int e = e0; e < e1; e++) {
        int s = g_srcl[e];
        uint2 v = t1v[(long long)s * 32 + lane];
        float2 a = __half22float2(*(__half2*)&v.x);
        float2 b = __half22float2(*(__half2*)&v.y);
        acc.x += a.x; acc.y += a.y; acc.z += b.x; acc.w += b.y;
    }
    float di = g_dinv[w];
    float4 bb = ((const float4*)b1)[lane];
    float4 r;
    r.x = fmaxf(fmaf(di, acc.x, bb.x), 0.0f);
    r.y = fmaxf(fmaf(di, acc.y, bb.y), 0.0f);
    r.z = fmaxf(fmaf(di, acc.z, bb.z), 0.0f);
    r.w = fmaxf(fmaf(di, acc.w, bb.w), 0.0f);
    ((float4*)g_r)[(long long)w * 32 + lane] = r;
}

// Pull layer 2: warp per node, 64 fp16 channels (1 uint = 2 halves per lane),
// serial loop, fp32 accumulate.
__global__ __launch_bounds__(256) void k_pull2(const float* __restrict__ b2,
                                               float* __restrict__ out, int n) {
    int w = (blockIdx.x * blockDim.x + threadIdx.x) >> 5;
    int lane = threadIdx.x & 31;
    if (w >= n) return;
    const unsigned* t2v = (const unsigned*)g_t2h;

    unsigned sv = t2v[(long long)w * 32 + lane];
    float2 acc = __half22float2(*(__half2*)&sv);

    int e0 = g_off[w], e1 = g_off[w + 1];
    for (int e = e0; e < e1; e++) {
        int s = g_srcl[e];
        unsigned v = t2v[(long long)s * 32 + lane];
        float2 a = __half22float2(*(__half2*)&v);
        acc.x += a.x; acc.y += a.y;
    }
    float di = g_dinv[w];
    float2 bb = ((const float2*)b2)[lane];
    float2 r;
    r.x = fmaf(di, acc.x, bb.x);
    r.y = fmaf(di, acc.y, bb.y);
    ((float2*)out)[(long long)w * 32 + lane] = r;
}

// ---------------------------------------------------------------------------
extern "C" void kernel_launch(void* const* d_in, const int* in_sizes, int n_in,
                              void* d_out, int out_size) {
    const float* x  = (const float*)d_in[0];
    const void*  ei = d_in[1];
    const float* W1 = (const float*)d_in[2];
    const float* b1 = (const float*)d_in[3];
    const float* W2 = (const float*)d_in[4];
    const float* b2 = (const float*)d_in[5];
    float* out = (float*)d_out;

    int N = in_sizes[0] / C1;            // 50000
    long long E = in_sizes[1] / 2;       // 800000

    void *p_t1h = nullptr, *p_r = nullptr, *p_t2h = nullptr;
    cudaGetSymbolAddress(&p_t1h, g_t1h);
    cudaGetSymbolAddress(&p_r,   g_r);
    cudaGetSymbolAddress(&p_t2h, g_t2h);

    k_detect<<<1, 32>>>(ei, N, E);

    int gN = (N + 255) / 256;
    long long gE = (E + 255) / 256;

    k_zero_cnt<<<gN, 256>>>(N);
    k_count<<<(unsigned)gE, 256>>>(ei, E);

    int nb = (N + 1023) / 1024;
    k_scan1<<<nb, 1024>>>(N);
    k_scan2<<<1, 64>>>(nb);
    k_scan3<<<gN, 256>>>(N, E);
    k_bucket<<<(unsigned)gE, 256>>>(ei, E);

    int gg = (N + 127) / 128;
    k_gemm_tf32<C1><<<gg, 256>>>(x, W1, (__half*)p_t1h, N);

    long long warpThreads = (long long)N * 32;
    int gw = (int)((warpThreads + 255) / 256);
    k_pull1<<<gw, 256>>>(b1, N);

    k_gemm_tf32<C2><<<gg, 256>>>((const float*)p_r, W2, (__half*)p_t2h, N);

    k_pull2<<<gw, 256>>>(b2, out, N);
}

// round 9
// speedup vs baseline: 1.4590x; 1.0031x over previous
#include <cuda_runtime.h>
#include <cuda_bf16.h>
#include <cuda_fp16.h>

// GCN 2-layer forward, pull-based aggregation via per-launch CSR build.
// GEMM1 (unscaled) runs on a forked capture stream, concurrent with CSR build.
//   t1h = fp16( x @ W1 )                          [tf32 GEMM, side stream]
//   r   = relu(dinv[i] * (dinv[i]*t1h[i] + sum dinv[s]*t1h[s]) + b1)
//   t2h = fp16( dinv[i] * (r @ W2) )              [tf32 GEMM]
//   out = dinv[i] * (t2h[i] + sum t2h[src]) + b2

#define MAXN 50000
#define MAXE 800000
#define C1 128
#define C2 64

__device__ int    g_is64;
__device__ int    g_cnt[MAXN];
__device__ int    g_off[MAXN + 1];
__device__ int    g_cur[MAXN];
__device__ int    g_srcl[MAXE];
__device__ int    g_part[64];
__device__ float  g_dinv[MAXN];
__device__ __half g_t1h[MAXN * C1];
__device__ float  g_r[MAXN * C1];
__device__ __half g_t2h[MAXN * C2];

// ---------------------------------------------------------------------------
__global__ void k_detect(const void* ei, int n_nodes, long long safe_words) {
    if (threadIdx.x == 0 && blockIdx.x == 0) {
        const unsigned long long* p = (const unsigned long long*)ei;
        long long cnt = safe_words < 64 ? safe_words : 64;
        int ok64 = 1;
        for (long long i = 0; i < cnt; i++) {
            if (p[i] >= (unsigned long long)n_nodes) { ok64 = 0; break; }
        }
        g_is64 = ok64;
    }
}

__device__ __forceinline__ int load_edge(const void* ei, long long idx, int is64) {
    if (is64) return (int)((const long long*)ei)[idx];
    return ((const int*)ei)[idx];
}

__global__ void k_zero_cnt(int n) {
    int i = blockIdx.x * blockDim.x + threadIdx.x;
    if (i < n) g_cnt[i] = 0;
}

__global__ void k_count(const void* ei, long long E) {
    long long e = (long long)blockIdx.x * blockDim.x + threadIdx.x;
    if (e < E) {
        int d = load_edge(ei, E + e, g_is64);
        atomicAdd(&g_cnt[d], 1);
    }
}

// Two-level exclusive scan of g_cnt -> g_off
__global__ void k_scan1(int n) {
    __shared__ int s[1024];
    int tid = threadIdx.x;
    int gid = blockIdx.x * 1024 + tid;
    int v = (gid < n) ? g_cnt[gid] : 0;
    s[tid] = v;
    __syncthreads();
#pragma unroll
    for (int o = 1; o < 1024; o <<= 1) {
        int t = (tid >= o) ? s[tid - o] : 0;
        __syncthreads();
        s[tid] += t;
        __syncthreads();
    }
    if (gid < n) g_off[gid] = s[tid] - v;
    if (tid == 1023) g_part[blockIdx.x] = s[tid];
}

__global__ void k_scan2(int nb) {
    __shared__ int s[64];
    int tid = threadIdx.x;
    int v = (tid < nb) ? g_part[tid] : 0;
    s[tid] = v;
    __syncthreads();
#pragma unroll
    for (int o = 1; o < 64; o <<= 1) {
        int t = (tid >= o) ? s[tid - o] : 0;
        __syncthreads();
        s[tid] += t;
        __syncthreads();
    }
    if (tid < nb) g_part[tid] = s[tid] - v;
}

__global__ void k_scan3(int n, long long E) {
    int i = blockIdx.x * blockDim.x + threadIdx.x;
    if (i < n) {
        int off = g_off[i] + g_part[i >> 10];
        g_off[i] = off;
        g_cur[i] = off;
        g_dinv[i] = rsqrtf((float)(g_cnt[i] + 1));
    }
    if (i == 0) g_off[n] = (int)E;
}

__global__ void k_bucket(const void* ei, long long E) {
    long long e = (long long)blockIdx.x * blockDim.x + threadIdx.x;
    if (e < E) {
        int is64 = g_is64;
        int s = load_edge(ei, e, is64);
        int d = load_edge(ei, E + e, is64);
        int pos = atomicAdd(&g_cur[d], 1);
        g_srcl[pos] = s;
    }
}

// ---------------------------------------------------------------------------
// tf32 tensor-core GEMM -> fp16 out. SCALE: multiply rows by g_dinv in epilogue.
__device__ __forceinline__ unsigned f2tf32(float f) {
    unsigned u;
    asm("cvt.rna.tf32.f32 %0, %1;" : "=r"(u) : "f"(f));
    return u;
}

template <int NC, bool SCALE>
__global__ __launch_bounds__(256) void k_gemm_tf32(
    const float* __restrict__ A, const float* __restrict__ W,
    __half* __restrict__ C, int M)
{
    constexpr int K   = 128;
    constexpr int BM  = 128;
    constexpr int BK  = 32;
    constexpr int PA  = BK + 4;
    constexpr int PB  = NC + 4;
    constexpr int NF  = NC / 16;

    __shared__ unsigned As[BM * PA];
    __shared__ unsigned Bs[BK * PB];

    int tid  = threadIdx.x;
    int wid  = tid >> 5;
    int lane = tid & 31;
    int wm   = wid >> 1;
    int wn   = wid & 1;
    int g    = lane >> 2;
    int t    = lane & 3;
    int rowBase = blockIdx.x * BM;

    float acc[2][NF][4];
#pragma unroll
    for (int mf = 0; mf < 2; mf++)
#pragma unroll
        for (int nf = 0; nf < NF; nf++)
#pragma unroll
            for (int i = 0; i < 4; i++) acc[mf][nf][i] = 0.0f;

    for (int kc = 0; kc < K; kc += BK) {
#pragma unroll
        for (int it = 0; it < (BM * BK / 4) / 256; it++) {
            int idx = tid + it * 256;
            int row = idx >> 3;
            int c4  = (idx & 7) * 4;
            int gr  = rowBase + row;
            float4 av = make_float4(0.f, 0.f, 0.f, 0.f);
            if (gr < M) av = *(const float4*)&A[(long long)gr * K + kc + c4];
            unsigned* dst = &As[row * PA + c4];
            dst[0] = f2tf32(av.x); dst[1] = f2tf32(av.y);
            dst[2] = f2tf32(av.z); dst[3] = f2tf32(av.w);
        }
#pragma unroll
        for (int it = 0; it < (BK * NC / 4) / 256; it++) {
            int idx = tid + it * 256;
            int row = idx / (NC / 4);
            int c4  = (idx % (NC / 4)) * 4;
            float4 bv = *(const float4*)&W[(kc + row) * NC + c4];
            unsigned* dst = &Bs[row * PB + c4];
            dst[0] = f2tf32(bv.x); dst[1] = f2tf32(bv.y);
            dst[2] = f2tf32(bv.z); dst[3] = f2tf32(bv.w);
        }
        __syncthreads();

#pragma unroll
        for (int kk = 0; kk < BK; kk += 8) {
            unsigned a[2][4];
#pragma unroll
            for (int mf = 0; mf < 2; mf++) {
                int r0 = wm * 32 + mf * 16;
                a[mf][0] = As[(r0 + g)     * PA + kk + t];
                a[mf][1] = As[(r0 + g + 8) * PA + kk + t];
                a[mf][2] = As[(r0 + g)     * PA + kk + t + 4];
                a[mf][3] = As[(r0 + g + 8) * PA + kk + t + 4];
            }
            unsigned b[NF][2];
#pragma unroll
            for (int nf = 0; nf < NF; nf++) {
                int c0 = wn * NF * 8 + nf * 8 + g;
                b[nf][0] = Bs[(kk + t)     * PB + c0];
                b[nf][1] = Bs[(kk + t + 4) * PB + c0];
            }
#pragma unroll
            for (int mf = 0; mf < 2; mf++)
#pragma unroll
                for (int nf = 0; nf < NF; nf++) {
                    asm volatile(
                        "mma.sync.aligned.m16n8k8.row.col.f32.tf32.tf32.f32 "
                        "{%0,%1,%2,%3}, {%4,%5,%6,%7}, {%8,%9}, {%0,%1,%2,%3};\n"
                        : "+f"(acc[mf][nf][0]), "+f"(acc[mf][nf][1]),
                          "+f"(acc[mf][nf][2]), "+f"(acc[mf][nf][3])
                        : "r"(a[mf][0]), "r"(a[mf][1]), "r"(a[mf][2]), "r"(a[mf][3]),
                          "r"(b[nf][0]), "r"(b[nf][1]));
                }
        }
        __syncthreads();
    }

#pragma unroll
    for (int mf = 0; mf < 2; mf++) {
        int r0 = rowBase + wm * 32 + mf * 16 + g;
        int r1 = r0 + 8;
        float d0 = 1.0f, d1 = 1.0f;
        if (SCALE) {
            d0 = (r0 < M) ? g_dinv[r0] : 0.f;
            d1 = (r1 < M) ? g_dinv[r1] : 0.f;
        }
#pragma unroll
        for (int nf = 0; nf < NF; nf++) {
            int col = wn * NF * 8 + nf * 8 + 2 * t;
            if (r0 < M) {
                __half2 h0 = __floats2half2_rn(d0 * acc[mf][nf][0], d0 * acc[mf][nf][1]);
                *(__half2*)&C[(long long)r0 * NC + col] = h0;
            }
            if (r1 < M) {
                __half2 h1 = __floats2half2_rn(d1 * acc[mf][nf][2], d1 * acc[mf][nf][3]);
                *(__half2*)&C[(long long)r1 * NC + col] = h1;
            }
        }
    }
}

// ---------------------------------------------------------------------------
// Pull layer 1: warp per node; t1h is UNSCALED -> apply dinv[s] per gathered row.
__global__ __launch_bounds__(256) void k_pull1(const float* __restrict__ b1, int n) {
    int w = (blockIdx.x * blockDim.x + threadIdx.x) >> 5;
    int lane = threadIdx.x & 31;
    if (w >= n) return;
    const uint2* t1v = (const uint2*)g_t1h;

    float diw = g_dinv[w];
    uint2 sv = t1v[(long long)w * 32 + lane];
    float2 f0 = __half22float2(*(__half2*)&sv.x);
    float2 f1 = __half22float2(*(__half2*)&sv.y);
    float4 acc = make_float4(diw * f0.x, diw * f0.y, diw * f1.x, diw * f1.y);

    int e0 = g_off[w], e1 = g_off[w + 1];
    for (int e = e0; e < e1; e++) {
        int s = g_srcl[e];
        float ds = g_dinv[s];
        uint2 v = t1v[(long long)s * 32 + lane];
        float2 a = __half22float2(*(__half2*)&v.x);
        float2 b = __half22float2(*(__half2*)&v.y);
        acc.x = fmaf(ds, a.x, acc.x);
        acc.y = fmaf(ds, a.y, acc.y);
        acc.z = fmaf(ds, b.x, acc.z);
        acc.w = fmaf(ds, b.y, acc.w);
    }
    float4 bb = ((const float4*)b1)[lane];
    float4 r;
    r.x = fmaxf(fmaf(diw, acc.x, bb.x), 0.0f);
    r.y = fmaxf(fmaf(diw, acc.y, bb.y), 0.0f);
    r.z = fmaxf(fmaf(diw, acc.z, bb.z), 0.0f);
    r.w = fmaxf(fmaf(diw, acc.w, bb.w), 0.0f);
    ((float4*)g_r)[(long long)w * 32 + lane] = r;
}

// Pull layer 2: warp per node, t2h pre-scaled by dinv[src] in GEMM2 epilogue.
__global__ __launch_bounds__(256) void k_pull2(const float* __restrict__ b2,
                                               float* __restrict__ out, int n) {
    int w = (blockIdx.x * blockDim.x + threadIdx.x) >> 5;
    int lane = threadIdx.x & 31;
    if (w >= n) return;
    const unsigned* t2v = (const unsigned*)g_t2h;

    unsigned sv = t2v[(long long)w * 32 + lane];
    float2 acc = __half22float2(*(__half2*)&sv);

    int e0 = g_off[w], e1 = g_off[w + 1];
    for (int e = e0; e < e1; e++) {
        int s = g_srcl[e];
        unsigned v = t2v[(long long)s * 32 + lane];
        float2 a = __half22float2(*(__half2*)&v);
        acc.x += a.x; acc.y += a.y;
    }
    float di = g_dinv[w];
    float2 bb = ((const float2*)b2)[lane];
    float2 r;
    r.x = fmaf(di, acc.x, bb.x);
    r.y = fmaf(di, acc.y, bb.y);
    ((float2*)out)[(long long)w * 32 + lane] = r;
}

// ---------------------------------------------------------------------------
extern "C" void kernel_launch(void* const* d_in, const int* in_sizes, int n_in,
                              void* d_out, int out_size) {
    const float* x  = (const float*)d_in[0];
    const void*  ei = d_in[1];
    const float* W1 = (const float*)d_in[2];
    const float* b1 = (const float*)d_in[3];
    const float* W2 = (const float*)d_in[4];
    const float* b2 = (const float*)d_in[5];
    float* out = (float*)d_out;

    int N = in_sizes[0] / C1;            // 50000
    long long E = in_sizes[1] / 2;       // 800000

    void *p_t1h = nullptr, *p_r = nullptr, *p_t2h = nullptr;
    cudaGetSymbolAddress(&p_t1h, g_t1h);
    cudaGetSymbolAddress(&p_r,   g_r);
    cudaGetSymbolAddress(&p_t2h, g_t2h);

    // Lazily-created side stream + events for forked capture (host resources,
    // no device memory; identical work every call).
    static cudaStream_t s2 = nullptr;
    static cudaEvent_t evFork = nullptr, evJoin = nullptr;
    if (!s2) {
        cudaStreamCreateWithFlags(&s2, cudaStreamNonBlocking);
        cudaEventCreateWithFlags(&evFork, cudaEventDisableTiming);
        cudaEventCreateWithFlags(&evJoin, cudaEventDisableTiming);
    }

    int gN = (N + 255) / 256;
    long long gE = (E + 255) / 256;
    int gg = (N + 127) / 128;

    // ---- fork: GEMM1 (no dinv dependency) on side stream ----
    cudaEventRecord(evFork, 0);
    cudaStreamWaitEvent(s2, evFork, 0);
    k_gemm_tf32<C1, false><<<gg, 256, 0, s2>>>(x, W1, (__half*)p_t1h, N);
    cudaEventRecord(evJoin, s2);

    // ---- main stream: CSR build chain ----
    k_detect<<<1, 32>>>(ei, N, E);
    k_zero_cnt<<<gN, 256>>>(N);
    k_count<<<(unsigned)gE, 256>>>(ei, E);

    int nb = (N + 1023) / 1024;
    k_scan1<<<nb, 1024>>>(N);
    k_scan2<<<1, 64>>>(nb);
    k_scan3<<<gN, 256>>>(N, E);
    k_bucket<<<(unsigned)gE, 256>>>(ei, E);

    // ---- join: pull1 needs t1h + CSR + dinv ----
    cudaStreamWaitEvent(0, evJoin, 0);

    long long warpThreads = (long long)N * 32;
    int gw = (int)((warpThreads + 255) / 256);
    k_pull1<<<gw, 256>>>(b1, N);

    k_gemm_tf32<C2, true><<<gg, 256>>>((const float*)p_r, W2, (__half*)p_t2h, N);

    k_pull2<<<gw, 256>>>(b2, out, N);
}